// round 17
// baseline (speedup 1.0000x reference)
#include <cuda_runtime.h>
#include <math.h>

#define B 128
#define C 6
#define H 224
#define W 224
#define HWSZ (H*W)          // 50176
#define HW4 (HWSZ/4)        // 12544 float4 per channel
#define POOL 7
#define NS (POOL*POOL)      // 49
#define BC (B*C)            // 768
#define CS (C*NS)           // 294
#define FEAT (3*C)          // 18
#define W4 (W/4)            // 56 float4 per row

__device__ float2 g_stats[BC];      // {scale, offset} per channel

__constant__ float c_prior[36] = {
    1.0f,  0.0f,  0.6f,  0.0f, -2.0f, 0.0f,
    0.0f,  1.0f,  0.6f,  0.0f,  0.0f, 0.0f,
    0.1f,  0.1f,  0.5f,  0.0f,  0.0f, 0.0f,
    0.0f,  0.0f,  0.0f,  1.0f,  0.0f, 0.0f,
    0.0f,  0.0f,  0.0f,  0.0f,  1.0f, 0.2f,
    0.0f, -0.6f, -0.6f, -0.6f,  0.6f, 1.0f
};
__constant__ float c_sign[6] = {1.f, -1.f, 1.f, -1.f, 1.f, 1.f};

__device__ __forceinline__ float tanh_f(float x) {
    float y;
    asm("tanh.approx.f32 %0, %1;" : "=f"(y) : "f"(x));
    return y;
}

// ---------------------------------------------------------------------------
// Kernel 1: pure streaming stats. One block per (b,c), 512 threads.
// Single phase = DRAM-bound regardless of block lockstep.
// ---------------------------------------------------------------------------
__global__ __launch_bounds__(512)
void stats_kernel(const float* __restrict__ x)
{
    __shared__ float ra[16], rb[16];
    const int bc = blockIdx.x;
    const float4* __restrict__ xin = (const float4*)(x + (size_t)bc * HWSZ);
    const int tid = threadIdx.x;
    const int warp = tid >> 5, lane = tid & 31;

    float sum = 0.f, sq = 0.f;
    #pragma unroll
    for (int base = 0; base < 24; base += 8) {
        float4 v[8];
        #pragma unroll
        for (int k = 0; k < 8; ++k) v[k] = xin[(base + k) * 512 + tid];
        #pragma unroll
        for (int k = 0; k < 8; ++k) {
            sum += (v[k].x + v[k].y) + (v[k].z + v[k].w);
            sq  += fmaf(v[k].x, v[k].x, fmaf(v[k].y, v[k].y,
                   fmaf(v[k].z, v[k].z, v[k].w * v[k].w)));
        }
    }
    if (tid < HW4 - 24 * 512) {         // tail: 256 float4
        float4 v = xin[24 * 512 + tid];
        sum += (v.x + v.y) + (v.z + v.w);
        sq  += fmaf(v.x, v.x, fmaf(v.y, v.y, fmaf(v.z, v.z, v.w * v.w)));
    }
    #pragma unroll
    for (int o = 16; o; o >>= 1) {
        sum += __shfl_down_sync(0xffffffffu, sum, o);
        sq  += __shfl_down_sync(0xffffffffu, sq,  o);
    }
    if (lane == 0) { ra[warp] = sum; rb[warp] = sq; }
    __syncthreads();
    if (warp == 0) {
        float s = (lane < 16) ? ra[lane] : 0.f;
        float q = (lane < 16) ? rb[lane] : 0.f;
        #pragma unroll
        for (int o = 8; o; o >>= 1) {
            s += __shfl_down_sync(0xffffffffu, s, o);
            q += __shfl_down_sync(0xffffffffu, q, o);
        }
        if (lane == 0) {
            const float invN = 1.0f / (float)HWSZ;
            float mean = s * invN;
            float var = fmaxf((q - s * s * invN) * (1.0f / (float)(HWSZ - 1)), 0.f);
            float is = 1.0f / (sqrtf(var) + 1e-5f);
            g_stats[bc] = make_float2(is, -mean * is);
        }
    }
}

// ---------------------------------------------------------------------------
// Kernel 2: per-BATCH fused gate+pool+mix+features+upsample. 128 blocks, 512
// threads. Stats precomputed -> no intra-kernel dependency.
//  A: 294 windows (6ch x 49) streamed from DRAM with tanh gate + 32x32 pool
//  B: all-channel graph mixing + features (in-block, tiny)
//  C: bilinear upsample of all 6 channels (154MB write chip-wide)
// ---------------------------------------------------------------------------
__global__ __launch_bounds__(512)
void fused2_kernel(const float* __restrict__ x,
                   const float* __restrict__ P_delta,
                   float* __restrict__ feat_out,
                   float* __restrict__ out)
{
    __shared__ float scs[C], ofs[C];
    __shared__ float pooled[CS], sal[CS], amat[CS], g2[CS];
    __shared__ float Pc[36], smean[C];
    __shared__ __align__(16) float4 hr4[C * POOL * W4];   // 6x7x56 float4 = 37.6KB

    const int b = blockIdx.x;
    const float* __restrict__ xb = x + (size_t)b * (C * HWSZ);
    const int tid = threadIdx.x;
    const int warp = tid >> 5, lane = tid & 31;

    if (tid < C) {
        float2 st = g_stats[b * C + tid];
        scs[tid] = st.x; ofs[tid] = st.y;
    }
    if (tid < 36) Pc[tid] = c_prior[tid] + 0.2f * tanhf(P_delta[tid]);
    __syncthreads();

    // ---- phase A: 294 windows, 16 warps stride 16 ----
    {
        const int sub = lane >> 3, c4 = lane & 7;
        for (int w = warp; w < CS; w += 16) {
            const int ch = w / NS, win = w - ch * NS;
            const float sc = scs[ch], of = ofs[ch];
            const int py = win / POOL, px = win - py * POOL;
            const float4* __restrict__ base =
                (const float4*)(xb + (size_t)ch * HWSZ
                                + (py * 32 + sub) * W + px * 32) + c4;
            float acc = 0.f;
            #pragma unroll
            for (int r = 0; r < 8; ++r) {        // rows sub, sub+4, ..., sub+28
                float4 u = base[r * W];
                acc += tanh_f(fmaf(u.x, sc, of));
                acc += tanh_f(fmaf(u.y, sc, of));
                acc += tanh_f(fmaf(u.z, sc, of));
                acc += tanh_f(fmaf(u.w, sc, of));
            }
            #pragma unroll
            for (int o = 16; o; o >>= 1)
                acc += __shfl_down_sync(0xffffffffu, acc, o);
            if (lane == 0) pooled[w] = acc * (1.0f / 2048.0f) + 0.5f;
        }
    }
    __syncthreads();

    // ---- phase B: mixing (all 6 concepts in-block) ----
    if (tid < C) {
        float m = 0.f;
        #pragma unroll
        for (int s = 0; s < NS; ++s) m += pooled[tid * NS + s];
        smean[tid] = m * (1.0f / (float)NS);
    }
    __syncthreads();

    if (tid < CS) {
        const int cc = tid / NS;
        sal[tid] = fmaxf(c_sign[cc] * (pooled[tid] - smean[cc]), 0.0f);
    }
    __syncthreads();

    if (tid < CS) {
        const int d = tid / NS, s = tid - d * NS;
        amat[tid] = sal[s]          * Pc[d]      + sal[NS + s]   * Pc[6 + d]
                  + sal[2*NS + s]   * Pc[12 + d] + sal[3*NS + s] * Pc[18 + d]
                  + sal[4*NS + s]   * Pc[24 + d] + sal[5*NS + s] * Pc[30 + d];
    }
    __syncthreads();

    if (tid < CS) {
        const int d = tid / NS, tt = tid - d * NS;
        const int ty = tt / POOL, tx = tt - ty * POOL;
        const float* am = amat + d * NS;
        float acc = 0.f;
        int s = 0;
        #pragma unroll
        for (int sy = 0; sy < POOL; ++sy) {
            const float dy2 = (float)((sy - ty) * (sy - ty));
            #pragma unroll
            for (int sx = 0; sx < POOL; ++sx, ++s) {
                const float dx = (float)(sx - tx);
                acc += __expf(-(dy2 + dx * dx) * 0.78125f) * am[s];
            }
        }
        g2[tid] = c_sign[d] * fmaxf(acc, 0.0f);
    }
    __syncthreads();

    // features: warp d (d<6) reduces its channel's 49 gsp values
    if (warp < C && lane < 32) {
        const int d = warp;
        float a  = g2[d * NS + (lane < NS ? lane : 0)];
        if (lane >= NS) a = g2[d * NS];          // lanes 49.. read dup of elem 0
        bool hi  = (lane + 32) < NS;
        float b2 = hi ? g2[d * NS + lane + 32] : a;
        float s  = (lane < NS ? a : 0.f) + (hi ? b2 : 0.f);
        float mx = fmaxf(a, hi ? b2 : a);
        float mn = fminf(a, hi ? b2 : a);
        #pragma unroll
        for (int o = 16; o; o >>= 1) {
            s  += __shfl_down_sync(0xffffffffu, s,  o);
            mx  = fmaxf(mx, __shfl_down_sync(0xffffffffu, mx, o));
            mn  = fminf(mn, __shfl_down_sync(0xffffffffu, mn, o));
        }
        if (lane == 0) {
            feat_out[b * FEAT + d]         = s * (1.0f / (float)NS);
            feat_out[b * FEAT + C + d]     = mx;
            feat_out[b * FEAT + 2 * C + d] = mn;
        }
    }

    // ---- phase C: horizontal tables for all 6 channels ----
    {
        float* hrows = (float*)hr4;              // [ch][r][j], row stride 224
        for (int i = tid; i < C * POOL * W; i += 512) {
            const int ch = i / (POOL * W);
            const int rem = i - ch * (POOL * W);
            const int r = rem / W, j = rem - r * W;
            const float sx = (j + 0.5f) * (1.0f / 32.0f) - 0.5f;
            const float x0f = floorf(sx);
            const float fx = sx - x0f;
            const int x0 = max(0, min(6, (int)x0f));
            const int x1 = max(0, min(6, (int)x0f + 1));
            const float a = g2[ch * NS + r * POOL + x0];
            hrows[i - j + j] = 0.f;              // (no-op to keep indexing clear)
            hrows[(ch * POOL + r) * W + j] = a + fx * (g2[ch * NS + r * POOL + x1] - a);
        }
    }
    __syncthreads();

    // vertical pass: 6 channels x 8 segments x 56 cols = 2688 items / 512 thr
    for (int it = tid; it < C * 448; it += 512) {
        const int ch = it / 448;
        const int rr = it - ch * 448;
        const int s  = rr / W4;          // 0..7 row segment
        const int c4 = rr - s * W4;      // 0..55
        const bool edge = (s == 0) | (s == 7);
        const int y0 = (s == 0) ? 0 : (s - 1);
        const int y1 = (s == 7) ? 6 : s;
        const int row0 = (s == 0) ? 0 : (32 * s - 16);
        const int n = edge ? 16 : 32;

        const float4 a  = hr4[(ch * POOL + y0) * W4 + c4];
        const float4 bb = hr4[(ch * POOL + y1) * W4 + c4];
        const float dxv = bb.x - a.x, dyv = bb.y - a.y;
        const float dzv = bb.z - a.z, dwv = bb.w - a.w;

        float4* __restrict__ o =
            (float4*)(out + (size_t)(b * C + ch) * HWSZ) + row0 * W4 + c4;
        #pragma unroll
        for (int r = 0; r < 32; ++r) {
            if (r < n) {
                const float fy = 0.015625f + (float)r * 0.03125f;
                float4 vv;
                vv.x = fmaf(fy, dxv, a.x);
                vv.y = fmaf(fy, dyv, a.y);
                vv.z = fmaf(fy, dzv, a.z);
                vv.w = fmaf(fy, dwv, a.w);
                __stcs(&o[r * W4], vv);
            }
        }
    }
}

// ---------------------------------------------------------------------------
extern "C" void kernel_launch(void* const* d_in, const int* in_sizes, int n_in,
                              void* d_out, int out_size)
{
    const float* x       = (const float*)d_in[0];   // (128,6,224,224) f32
    const float* P_delta = (const float*)d_in[1];   // (6,6) f32
    float* out = (float*)d_out;                     // [B*18 | B*C*H*W]

    stats_kernel<<<BC, 512>>>(x);
    fused2_kernel<<<B, 512>>>(x, P_delta, out, out + (size_t)B * FEAT);
}